// round 14
// baseline (speedup 1.0000x reference)
#include <cuda_runtime.h>
#include <cuda_bf16.h>
#include <cstdint>

#define Bc 8
#define Nc 1024
#define Hc 512
#define NHEADS 8
#define HD 64
#define LN_EPS 1e-5f
#define LOG2E 1.44269504088896f

typedef __nv_bfloat16 bf16;

// ---------------- scratch ------------------------------------------------------
__device__ bf16  g_xb[Bc * Nc * Hc];
__device__ bf16  g_wb[3 * Hc * Hc];
__device__ bf16  g_q[Bc * NHEADS * Nc * HD];             // [bh][n][d] (pre-scaled by log2e)
__device__ bf16  g_k[Bc * NHEADS * Nc * HD];
__device__ bf16  g_z0[Bc * NHEADS * HD * Nc];            // v, d-major [bh][d][n]
__device__ bf16  g_P[(size_t)Bc * NHEADS * Nc * Nc];     // exp(scores), 128MB
__device__ float g_rowsum[Bc * NHEADS * Nc];
__device__ unsigned g_adjbits[Bc * Nc * 32];
__device__ bf16  g_zA[Bc * NHEADS * HD * Nc];            // d-major intermediates
__device__ bf16  g_zC[Bc * NHEADS * HD * Nc];
__device__ bf16  g_zB[Bc * NHEADS * Nc * HD];            // final, token-major bf16

// ---------------- helpers ------------------------------------------------------
__device__ __forceinline__ void mma_bf16(float c[4],
    unsigned a0, unsigned a1, unsigned a2, unsigned a3,
    unsigned b0, unsigned b1)
{
    asm("mma.sync.aligned.m16n8k16.row.col.f32.bf16.bf16.f32 "
        "{%0,%1,%2,%3},{%4,%5,%6,%7},{%8,%9},{%0,%1,%2,%3};"
        : "+f"(c[0]), "+f"(c[1]), "+f"(c[2]), "+f"(c[3])
        : "r"(a0), "r"(a1), "r"(a2), "r"(a3), "r"(b0), "r"(b1));
}
__device__ __forceinline__ void ldsm4(unsigned r[4], unsigned addr) {
    asm volatile("ldmatrix.sync.aligned.m8n8.x4.shared.b16 {%0,%1,%2,%3}, [%4];"
        : "=r"(r[0]), "=r"(r[1]), "=r"(r[2]), "=r"(r[3]) : "r"(addr));
}
__device__ __forceinline__ void stsm4(unsigned addr,
    unsigned r0, unsigned r1, unsigned r2, unsigned r3)
{
    asm volatile("stmatrix.sync.aligned.m8n8.x4.shared.b16 [%0], {%1,%2,%3,%4};"
        :: "r"(addr), "r"(r0), "r"(r1), "r"(r2), "r"(r3));
}
__device__ __forceinline__ void cp16(unsigned smem_dst, const void* gsrc) {
    asm volatile("cp.async.cg.shared.global [%0], [%1], 16;"
                 :: "r"(smem_dst), "l"(gsrc));
}
__device__ __forceinline__ void cp_commit() {
    asm volatile("cp.async.commit_group;");
}
template<int N> __device__ __forceinline__ void cp_wait() {
    asm volatile("cp.async.wait_group %0;" :: "n"(N));
}
__device__ __forceinline__ unsigned packbf(float x, float y) {
    __nv_bfloat162 p;
    p.x = __float2bfloat16_rn(x);
    p.y = __float2bfloat16_rn(y);
    return *(unsigned*)&p;
}

// ---------------- kernel A: fused prologue (pack_adj + cvt bf16) ---------------
#define NX4 (Bc * Nc * Hc / 4)
#define NW4 (Hc * Hc / 4)
#define PACK_BLKS ((Bc * Nc * 32 * 32) / 256)
__global__ __launch_bounds__(256) void prologue_kernel(
    const float4* __restrict__ x,
    const float4* __restrict__ wq, const float4* __restrict__ wk,
    const float4* __restrict__ wv, const int* __restrict__ adj,
    __nv_bfloat162* __restrict__ xb, __nv_bfloat162* __restrict__ wb,
    unsigned* __restrict__ bits)
{
    int blk = blockIdx.x;
    if (blk < PACK_BLKS) {
        int gt = blk * 256 + threadIdx.x;
        int gw = gt >> 5;
        int lane = gt & 31;
        int row = gw >> 5;
        int col = (gw & 31) * 32 + lane;
        int v = adj[(size_t)row * Nc + col];
        unsigned m = __ballot_sync(0xffffffffu, v != 0);
        if (lane == 0) bits[gw] = m;
        return;
    }
    int i = (blk - PACK_BLKS) * 256 + threadIdx.x;
    const float4* src;
    __nv_bfloat162* dst;
    int off;
    if (i < NX4)               { src = x;  dst = xb;            off = i; }
    else if (i < NX4 + NW4)    { src = wq; dst = wb;            off = i - NX4; }
    else if (i < NX4 + 2*NW4)  { src = wk; dst = wb + 2*NW4;    off = i - NX4 - NW4; }
    else                       { src = wv; dst = wb + 4*NW4;    off = i - NX4 - 2*NW4; }
    float4 v = src[off];
    __nv_bfloat162 a, b;
    a.x = __float2bfloat16_rn(v.x); a.y = __float2bfloat16_rn(v.y);
    b.x = __float2bfloat16_rn(v.z); b.y = __float2bfloat16_rn(v.w);
    dst[2 * off] = a; dst[2 * off + 1] = b;
}

// ---------------- kernel 1: QKV GEMM, all-bf16, ldmatrix fragments -------------
#define QSTG_W (128 * 32)                 // one 128x64 bf16 swizzled tile (words)
__global__ __launch_bounds__(256) void qkv_kernel(
    const bf16* __restrict__ Xb, const bf16* __restrict__ Wb,
    const float* __restrict__ bq, const float* __restrict__ bk,
    const float* __restrict__ bv,
    bf16* __restrict__ outq, bf16* __restrict__ outk, bf16* __restrict__ outv)
{
    const int which = blockIdx.z;
    const bf16* W = Wb + (size_t)which * Hc * Hc;
    const float* bias = which == 0 ? bq : which == 1 ? bk : bv;

    __shared__ uint32_t smemq[2 * QSTG_W];     // Xs | Ws, 32KB
    unsigned xbyte = (unsigned)__cvta_generic_to_shared(smemq);
    unsigned wbyte = xbyte + QSTG_W * 4;

    const int tid = threadIdx.x;
    const int wid = tid >> 5, lane = tid & 31;
    const int g = lane >> 2, t = lane & 3;
    const int warpM = (wid >> 1) * 32;
    const int warpN = (wid & 1) * 64;
    const int mBase = blockIdx.y * 128;
    const int nBase = blockIdx.x * 128;

    // ldmatrix lane invariants (validated in hop kernel)
    const int l15 = lane & 15;
    const int selA = lane >> 4;
    const int xorA = l15 & 7;
    const int q4 = lane >> 3;
    const int selB = q4 & 1;
    const int rBoff = ((q4 >> 1) << 3) + (lane & 7);
    const int xorB = lane & 7;
    const unsigned baseA0 = (unsigned)(warpM + l15) * 128;
    const unsigned baseA1 = baseA0 + 2048;

    float acc[2][8][4] = {};

    for (int k0 = 0; k0 < Hc; k0 += 64) {
        #pragma unroll
        for (int it = 0; it < 4; it++) {
            int j = tid + it * 256;
            int r = j >> 3, ch = j & 7;
            *(uint4*)&smemq[(r * 8 + (ch ^ (r & 7))) * 4] =
                *(const uint4*)&Xb[(size_t)(mBase + r) * Hc + k0 + ch * 8];
            *(uint4*)&smemq[QSTG_W + (r * 8 + (ch ^ (r & 7))) * 4] =
                *(const uint4*)&W[(size_t)(nBase + r) * Hc + k0 + ch * 8];
        }
        __syncthreads();
        #pragma unroll
        for (int ksi = 0; ksi < 4; ksi++) {
            const int cc = ksi * 2;
            unsigned aA0[4], aA1[4];
            ldsm4(aA0, xbyte + baseA0 + ((unsigned)((cc + selA) ^ xorA) << 4));
            ldsm4(aA1, xbyte + baseA1 + ((unsigned)((cc + selA) ^ xorA) << 4));
            #pragma unroll
            for (int grp = 0; grp < 4; grp++) {
                unsigned bf[4];
                ldsm4(bf, wbyte + (unsigned)(warpN + grp * 16 + rBoff) * 128 +
                          ((unsigned)((cc + selB) ^ xorB) << 4));
                mma_bf16(acc[0][2 * grp],     aA0[0], aA0[1], aA0[2], aA0[3], bf[0], bf[1]);
                mma_bf16(acc[0][2 * grp + 1], aA0[0], aA0[1], aA0[2], aA0[3], bf[2], bf[3]);
                mma_bf16(acc[1][2 * grp],     aA1[0], aA1[1], aA1[2], aA1[3], bf[0], bf[1]);
                mma_bf16(acc[1][2 * grp + 1], aA1[0], aA1[1], aA1[2], aA1[3], bf[2], bf[3]);
            }
        }
        __syncthreads();
    }

    const float qscale = (which == 0) ? LOG2E : 1.0f;
    #pragma unroll
    for (int mf = 0; mf < 2; mf++)
        #pragma unroll
        for (int nf = 0; nf < 8; nf++)
            #pragma unroll
            for (int half = 0; half < 2; half++) {
                int row = mBase + warpM + mf * 16 + g + half * 8;
                int col = nBase + warpN + nf * 8 + 2 * t;
                float v0 = (acc[mf][nf][half * 2 + 0] + bias[col]) * qscale;
                float v1 = (acc[mf][nf][half * 2 + 1] + bias[col + 1]) * qscale;
                int btok = row >> 10, ntok = row & 1023;
                int h = col >> 6, d = col & 63;
                int bh = btok * NHEADS + h;
                if (which == 2) {
                    outv[((size_t)bh * HD + d) * Nc + ntok] = __float2bfloat16_rn(v0);
                    outv[((size_t)bh * HD + d + 1) * Nc + ntok] = __float2bfloat16_rn(v1);
                } else {
                    bf16* out = which == 0 ? outq : outk;
                    __nv_bfloat162 pr;
                    pr.x = __float2bfloat16_rn(v0);
                    pr.y = __float2bfloat16_rn(v1);
                    *(__nv_bfloat162*)&out[((size_t)bh * Nc + ntok) * HD + d] = pr;
                }
            }
}

// ---------------- kernel 2: scores + hop1 fused, ldmatrix + stmatrix -----------
#define FQ_W (128 * 36)
#define FK2_W (128 * 32)
#define FZ2_W (64 * 64)
#define PSTG_W (128 * 32)
#define FS_SMEM ((FQ_W + 2 * FK2_W + 2 * FZ2_W + PSTG_W) * 4)   // 100352 B

__global__ __launch_bounds__(256, 2) void scores_hop1_kernel(
    const bf16* __restrict__ q, const bf16* __restrict__ k,
    const bf16* __restrict__ z0_tr, const unsigned* __restrict__ adjbits,
    bf16* __restrict__ P, float* __restrict__ rowsum, bf16* __restrict__ z1)
{
    extern __shared__ __align__(16) char smem[];
    uint32_t* Qs = (uint32_t*)smem;
    unsigned sbase = (unsigned)__cvta_generic_to_shared(smem);
    const unsigned kbase = sbase + FQ_W * 4;
    const unsigned zbase = kbase + 2 * FK2_W * 4;
    const unsigned pstg = zbase + 2 * FZ2_W * 4;
    const uint32_t* stw = (const uint32_t*)(smem + (FQ_W + 2 * FK2_W + 2 * FZ2_W) * 4);

    const int bh = blockIdx.y;
    const int b = bh >> 3;
    const int nBase = blockIdx.x * 128;

    const int tid = threadIdx.x;
    const int wid = tid >> 5, lane = tid & 31;
    const int g = lane >> 2, t = lane & 3;
    const int warpRow = wid * 16;

    const bf16* qb = q + (size_t)bh * Nc * HD;
    const bf16* kb = k + (size_t)bh * Nc * HD;
    const bf16* zi = z0_tr + (size_t)bh * HD * Nc;

    const int q4 = lane >> 3;
    const int selB = q4 & 1;
    const int rBoff = ((q4 >> 1) << 3) + (lane & 7);
    const int xorB = lane & 7;
    const int lr8 = lane & 7;
    const int lm = lane >> 3;

    #pragma unroll
    for (int it = 0; it < 4; it++) {
        int j = tid + it * 256;
        int r = j >> 3, c = j & 7;
        *(uint4*)&Qs[r * 36 + c * 4] =
            *(const uint4*)&qb[(size_t)(nBase + r) * HD + c * 8];
    }

    auto loadKZ = [&](int ct, int s) {
        unsigned kb2 = kbase + s * (FK2_W * 4);
        #pragma unroll
        for (int j = 0; j < 4; j++) {
            int e = tid + j * 256;
            int r = e >> 3, c = e & 7;
            cp16(kb2 + (r * 8 + (c ^ (r & 7))) * 16,
                 kb + (size_t)(ct * 128 + r) * HD + c * 8);
        }
        unsigned zb2 = zbase + s * (FZ2_W * 4);
        #pragma unroll
        for (int j = 0; j < 4; j++) {
            int e = tid + j * 256;
            int d = e >> 4, c = e & 15;
            cp16(zb2 + (d * 16 + ((c & 8) | ((c & 7) ^ (d & 7)))) * 16,
                 zi + (size_t)d * Nc + ct * 128 + c * 8);
        }
        cp_commit();
    };
    loadKZ(0, 0);
    loadKZ(1, 1);
    __syncthreads();

    unsigned qf[4][4];
    #pragma unroll
    for (int ks = 0; ks < 4; ks++) {
        int r0 = warpRow + g;
        qf[ks][0] = Qs[r0 * 36 + ks * 8 + t];
        qf[ks][1] = Qs[(r0 + 8) * 36 + ks * 8 + t];
        qf[ks][2] = Qs[r0 * 36 + ks * 8 + t + 4];
        qf[ks][3] = Qs[(r0 + 8) * 36 + ks * 8 + t + 4];
    }

    const unsigned* bitsb = adjbits + (size_t)b * Nc * 32;
    bf16* Pb = P + (size_t)bh * Nc * Nc;
    const int row_g = nBase + warpRow + g;
    const int row_h = row_g + 8;
    const int tshift = 2 * t;

    float accz[8][4] = {};
    float rs_g = 0.f, rs_h = 0.f;

    for (int ct = 0; ct < 8; ct++) {
        if (ct < 7) cp_wait<1>(); else cp_wait<0>();
        __syncthreads();
        const int buf = ct & 1;
        const unsigned kbyte = kbase + buf * (FK2_W * 4);
        const unsigned zbyte = zbase + buf * (FZ2_W * 4);

        #pragma unroll
        for (int half = 0; half < 2; half++) {
            // ---- scores MMA ----
            float accs[8][4] = {};
            #pragma unroll
            for (int ksi = 0; ksi < 4; ksi++) {
                const unsigned chsw = (unsigned)((ksi * 2 + selB) ^ xorB) << 4;
                #pragma unroll
                for (int grp = 0; grp < 4; grp++) {
                    unsigned kf[4];
                    ldsm4(kf, kbyte + (unsigned)(half * 64 + grp * 16 + rBoff) * 128 + chsw);
                    mma_bf16(accs[2 * grp],     qf[ksi][0], qf[ksi][1], qf[ksi][2], qf[ksi][3], kf[0], kf[1]);
                    mma_bf16(accs[2 * grp + 1], qf[ksi][0], qf[ksi][1], qf[ksi][2], qf[ksi][3], kf[2], kf[3]);
                }
            }

            // ---- mask + exp2 + pack ----
            unsigned prg[8], prh[8];
            unsigned m0g = bitsb[(size_t)row_g * 32 + ct * 4 + half * 2] >> tshift;
            unsigned m1g = bitsb[(size_t)row_g * 32 + ct * 4 + half * 2 + 1] >> tshift;
            unsigned m0h = bitsb[(size_t)row_h * 32 + ct * 4 + half * 2] >> tshift;
            unsigned m1h = bitsb[(size_t)row_h * 32 + ct * 4 + half * 2 + 1] >> tshift;
            #pragma unroll
            for (int nf = 0; nf < 8; nf++) {
                unsigned mg_ = ((nf < 4) ? m0g : m1g) >> ((nf & 3) * 8);
                unsigned mh_ = ((nf < 4) ? m0h : m1h) >> ((nf & 3) * 8);
                float e0 = (mg_ & 1u) ? exp2f(accs[nf][0]) : 0.f;
                float e1 = (mg_ & 2u) ? exp2f(accs[nf][1]) : 0.f;
                float e2 = (mh_ & 1u) ? exp2f(accs[nf][2]) : 0.f;
                float e3 = (mh_ & 2u) ? exp2f(accs[nf][3]) : 0.f;
                prg[nf] = packbf(e0, e1);
                prh[nf] = packbf(e2, e3);
                rs_g += e0 + e1;
                rs_h += e2 + e3;
            }

            // ---- stmatrix stage (issued early; latency hidden under z-MMA) ----
            {
                int r1 = warpRow + lr8;
                int r2 = r1 + 8;
                stsm4(pstg + (unsigned)(r1 * 8 + (lm ^ (r1 & 7))) * 16,
                      prg[0], prg[1], prg[2], prg[3]);
                stsm4(pstg + (unsigned)(r1 * 8 + ((4 + lm) ^ (r1 & 7))) * 16,
                      prg[4], prg[5], prg[6], prg[7]);
                stsm4(pstg + (unsigned)(r2 * 8 + (lm ^ (r2 & 7))) * 16,
                      prh[0], prh[1], prh[2], prh[3]);
                stsm4(pstg + (unsigned)(r2 * 8 + ((4 + lm) ^ (r2 & 7))) * 16,
                      prh[4], prh[5], prh[6], prh[7]);
            }

            // ---- z-MMA: A = exp fragments, B = z0 via ldmatrix ----
            #pragma unroll
            for (int kc = 0; kc < 4; kc++) {
                unsigned a0 = prg[2 * kc], a1 = prh[2 * kc];
                unsigned a2 = prg[2 * kc + 1], a3 = prh[2 * kc + 1];
                const unsigned chsw = (unsigned)((half * 8 + kc * 2 + selB) ^ xorB) << 4;
                #pragma unroll
                for (int grp = 0; grp < 4; grp++) {
                    unsigned zf[4];
                    ldsm4(zf, zbyte + (unsigned)(grp * 16 + rBoff) * 256 + chsw);
                    mma_bf16(accz[2 * grp],     a0, a1, a2, a3, zf[0], zf[1]);
                    mma_bf16(accz[2 * grp + 1], a0, a1, a2, a3, zf[2], zf[3]);
                }
            }

            // ---- P store: readback + coalesced STG.128 ----
            {
                __syncwarp();
                #pragma unroll
                for (int i = 0; i < 4; i++) {
                    int idx = i * 32 + lane;
                    int lr = warpRow + (idx >> 3);
                    int ch = idx & 7;
                    uint4 v = *(const uint4*)&stw[(lr * 8 + (ch ^ (lr & 7))) * 4];
                    *(uint4*)&Pb[(size_t)(nBase + lr) * Nc + ct * 128 + half * 64 + ch * 8] = v;
                }
                __syncwarp();
            }
        }
        __syncthreads();
        if (ct + 2 < 8) loadKZ(ct + 2, buf);
    }

    rs_g += __shfl_xor_sync(0xffffffffu, rs_g, 1);
    rs_g += __shfl_xor_sync(0xffffffffu, rs_g, 2);
    rs_h += __shfl_xor_sync(0xffffffffu, rs_h, 1);
    rs_h += __shfl_xor_sync(0xffffffffu, rs_h, 2);
    if (t == 0) {
        rowsum[(size_t)bh * Nc + row_g] = rs_g;
        rowsum[(size_t)bh * Nc + row_h] = rs_h;
    }

    float sc_g = 0.9f / rs_g, sc_h = 0.9f / rs_h;
    bf16* zo = z1 + (size_t)bh * HD * Nc;
    #pragma unroll
    for (int nd = 0; nd < 8; nd++) {
        int d0 = nd * 8 + 2 * t;
        float zg0 = __bfloat162float(zi[(size_t)d0 * Nc + row_g]);
        float zg1 = __bfloat162float(zi[(size_t)(d0 + 1) * Nc + row_g]);
        float zh0 = __bfloat162float(zi[(size_t)d0 * Nc + row_h]);
        float zh1 = __bfloat162float(zi[(size_t)(d0 + 1) * Nc + row_h]);
        zo[(size_t)d0 * Nc + row_g]       = __float2bfloat16_rn(accz[nd][0] * sc_g + 0.1f * zg0);
        zo[(size_t)(d0 + 1) * Nc + row_g] = __float2bfloat16_rn(accz[nd][1] * sc_g + 0.1f * zg1);
        zo[(size_t)d0 * Nc + row_h]       = __float2bfloat16_rn(accz[nd][2] * sc_h + 0.1f * zh0);
        zo[(size_t)(d0 + 1) * Nc + row_h] = __float2bfloat16_rn(accz[nd][3] * sc_h + 0.1f * zh1);
    }
}

// ---------------- kernel 3: hop, K=64 2-stage swizzled, ldmatrix, 4 CTA/SM -----
#define PSW_W (128 * 32)
#define ZSW_W (64 * 32)
#define STG_W (PSW_W + ZSW_W)            // 24576 B
#define HOP_SMEM (2 * STG_W * 4)         // 49152 B

template<bool LAST>
__global__ __launch_bounds__(256, 4) void hop_kernel8(
    const bf16* __restrict__ Pg, const float* __restrict__ rowsum,
    const bf16* __restrict__ zin_tr, const bf16* __restrict__ z0_tr,
    void* __restrict__ zout, int rev)
{
    extern __shared__ __align__(16) char smem[];
    unsigned sbase = (unsigned)__cvta_generic_to_shared(smem);

    int lin = blockIdx.y * gridDim.x + blockIdx.x;
    if (rev) lin = 511 - lin;
    const int bh = lin >> 3;
    const int mBase = (lin & 7) * 128;

    const bf16* Pb = Pg + (size_t)bh * Nc * Nc;
    const bf16* zi = zin_tr + (size_t)bh * HD * Nc;

    const int tid = threadIdx.x;
    const int wid = tid >> 5, lane = tid & 31;
    const int g = lane >> 2, t = lane & 3;
    const int warpM = (wid >> 1) * 32;
    const int warpN = (wid & 1) * 32;

    const int l15 = lane & 15;
    const int selA = lane >> 4;
    const int xorA = l15 & 7;
    const int q4 = lane >> 3;
    const int selB = q4 & 1;
    const int rBoff = ((q4 >> 1) << 3) + (lane & 7);
    const int xorB = lane & 7;
    const unsigned baseA0 = (unsigned)(warpM + l15) * 128;
    const unsigned baseA1 = baseA0 + 2048;
    const unsigned baseB0 = (unsigned)(warpN + rBoff) * 128;
    const unsigned baseB1 = baseB0 + 2048;

    auto load_chunk = [&](int ck, int s) {
        unsigned pbase = sbase + s * (STG_W * 4);
        unsigned zbase = pbase + PSW_W * 4;
        const int k0 = ck * 64;
        #pragma unroll
        for (int j = 0; j < 4; j++) {
            int e = tid + j * 256;
            int r = e >> 3, ch = e & 7;
            cp16(pbase + (r * 8 + (ch ^ (r & 7))) * 16,
                 Pb + (size_t)(mBase + r) * Nc + k0 + ch * 8);
        }
        #pragma unroll
        for (int j = 0; j < 2; j++) {
            int e = tid + j * 256;
            int d = e >> 3, ch = e & 7;
            cp16(zbase + (d * 8 + (ch ^ (d & 7))) * 16,
                 zi + (size_t)d * Nc + k0 + ch * 8);
        }
        cp_commit();
    };

    load_chunk(0, 0);
    load_chunk(1, 1);

    float acc[2][4][4] = {};

    for (int c = 0; c < 16; c++) {
        if (c < 15) cp_wait<1>(); else cp_wait<0>();
        __syncthreads();
        const int st = c & 1;
        const unsigned pbyte = sbase + st * (STG_W * 4);
        const unsigned zbyte = pbyte + PSW_W * 4;
        #pragma unroll
        for (int ks = 0; ks < 32; ks += 8) {
            const int cc = ks >> 2;
            unsigned aA0[4], aA1[4], bB0[4], bB1[4];
            ldsm4(aA0, pbyte + baseA0 + ((unsigned)((cc + selA) ^ xorA) << 4));
            ldsm4(aA1, pbyte + baseA1 + ((unsigned)((cc + selA) ^ xorA) << 4));
            ldsm4(bB0, zbyte + baseB0 + ((unsigned)((cc + selB) ^ xorB) << 4));
            ldsm4(bB1, zbyte + baseB1 + ((unsigned)((cc + selB) ^ xorB) << 4));
            mma_bf16(acc[0][0], aA0[0], aA0[1], aA0[2], aA0[3], bB0[0], bB0[1]);
            mma_bf16(acc[0][1], aA0[0], aA0[1], aA0[2], aA0[3], bB0[2], bB0[3]);
            mma_bf16(acc[0][2], aA0[0], aA0[1], aA0[2], aA0[3], bB1[0], bB1[1]);
            mma_bf16(acc[0][3], aA0[0], aA0[1], aA0[2], aA0[3], bB1[2], bB1[3]);
            mma_bf16(acc[1][0], aA1[0], aA1[1], aA1[2], aA1[3], bB0[0], bB0[1]);
            mma_bf16(acc[1][1], aA1[0], aA1[1], aA1[2], aA1[3], bB0[2], bB0[3]);
            mma_bf16(acc[1][2], aA1[0], aA1[1], aA1[2], aA1[3], bB1[0], bB1[1]);
            mma_bf16(acc[1][3], aA1[0], aA1[1], aA1[2], aA1[3], bB1[2], bB1[3]);
        }
        __syncthreads();
        if (c + 2 < 16) load_chunk(c + 2, st);
    }

    #pragma unroll
    for (int mf = 0; mf < 2; mf++)
        #pragma unroll
        for (int half = 0; half < 2; half++) {
            int row = mBase + warpM + mf * 16 + g + half * 8;
            float scale = 0.9f / rowsum[(size_t)bh * Nc + row];
            #pragma unroll
            for (int nf = 0; nf < 4; nf++) {
                int col = warpN + nf * 8 + 2 * t;
                float z00 = __bfloat162float(z0_tr[((size_t)bh * HD + col) * Nc + row]);
                float z01 = __bfloat162float(z0_tr[((size_t)bh * HD + col + 1) * Nc + row]);
                float v0 = acc[mf][nf][half * 2 + 0] * scale + 0.1f * z00;
                float v1 = acc[mf][nf][half * 2 + 1] * scale + 0.1f * z01;
                if (LAST) {
                    bf16* zf = (bf16*)zout;
                    *(unsigned*)&zf[((size_t)bh * Nc + row) * HD + col] = packbf(v0, v1);
                } else {
                    bf16* zo = (bf16*)zout;
                    zo[((size_t)bh * HD + col) * Nc + row] = __float2bfloat16_rn(v0);
                    zo[((size_t)bh * HD + col + 1) * Nc + row] = __float2bfloat16_rn(v1);
                }
            }
        }
}

// ---------------- kernel 4: residual + layernorm (warp-per-row) ---------------
__global__ __launch_bounds__(256) void out_kernel(
    const float* __restrict__ x, const bf16* __restrict__ z,
    const float* __restrict__ gamma, const float* __restrict__ beta,
    float* __restrict__ out)
{
    const int wid = threadIdx.x >> 5, lane = threadIdx.x & 31;
    const int row = blockIdx.x * 8 + wid;
    const int b = row >> 10, n = row & (Nc - 1);

    const float4* xr = (const float4*)(x + (size_t)row * Hc);
    float y[16];
    float s = 0.f, s2 = 0.f;
    #pragma unroll
    for (int j = 0; j < 4; j++) {
        int f4 = j * 32 + lane;
        float4 xv = xr[f4];
        int e = f4 * 4;
        int h = e >> 6, d = e & 63;
        const bf16* zp = z + (((size_t)b * NHEADS + h) * Nc + n) * HD + d;
        uint2 zv = *(const uint2*)zp;
        __nv_bfloat162 z01 = *(__nv_bfloat162*)&zv.x;
        __nv_bfloat162 z23 = *(__nv_bfloat162*)&zv.y;
        float y0 = xv.x + __bfloat162float(z01.x);
        float y1 = xv.y + __bfloat162float(z01.y);
        float y2 = xv.z + __bfloat162float(z23.x);
        float y3 = xv.w + __bfloat162float(z23.y);
        y[j*4+0] = y0; y[j*4+1] = y1; y[j*4+2] = y2; y[j*4+3] = y3;
        s += y0 + y1 + y2 + y3;
        s2 += y0*y0 + y1*y1 + y2*y2 + y3*y3;
    }
    #pragma unroll
    for (int o = 16; o > 0; o >>= 1) {
        s  += __shfl_xor_sync(0xffffffffu, s, o);
        s2 += __shfl_xor_sync(0xffffffffu, s2, o);
    }
    float mu = s * (1.0f / Hc);
    float var = s2 * (1.0f / Hc) - mu * mu;
    float rstd = rsqrtf(var + LN_EPS);

    const float4* gm = (const float4*)gamma;
    const float4* bt = (const float4*)beta;
    float4* outr = (float4*)(out + (size_t)row * Hc);
    #pragma unroll
    for (int j = 0; j < 4; j++) {
        int f4 = j * 32 + lane;
        float4 gv = gm[f4], bv = bt[f4];
        float4 ov;
        ov.x = (y[j*4+0] - mu) * rstd * gv.x + bv.x;
        ov.y = (y[j*4+1] - mu) * rstd * gv.y + bv.y;
        ov.z = (y[j*4+2] - mu) * rstd * gv.z + bv.z;
        ov.w = (y[j*4+3] - mu) * rstd * gv.w + bv.w;
        outr[f4] = ov;
    }
}

// ---------------- launch -------------------------------------------------------
extern "C" void kernel_launch(void* const* d_in, const int* in_sizes, int n_in,
                              void* d_out, int out_size)
{
    const float* x     = (const float*)d_in[0];
    const int*   adj   = (const int*)d_in[1];
    const float* Wq    = (const float*)d_in[2];
    const float* bq    = (const float*)d_in[3];
    const float* Wk    = (const float*)d_in[4];
    const float* bk    = (const float*)d_in[5];
    const float* Wv    = (const float*)d_in[6];
    const float* bv    = (const float*)d_in[7];
    const float* gamma = (const float*)d_in[8];
    const float* beta  = (const float*)d_in[9];
    float* out = (float*)d_out;

    float* prs;
    bf16 *pxb, *pwb, *pq, *pk, *pz0, *pP, *pzA, *pzC, *pzB;
    unsigned* pbits;
    cudaGetSymbolAddress((void**)&pxb,  g_xb);
    cudaGetSymbolAddress((void**)&pwb,  g_wb);
    cudaGetSymbolAddress((void**)&pq,   g_q);
    cudaGetSymbolAddress((void**)&pk,   g_k);
    cudaGetSymbolAddress((void**)&pz0,  g_z0);
    cudaGetSymbolAddress((void**)&pP,   g_P);
    cudaGetSymbolAddress((void**)&prs,  g_rowsum);
    cudaGetSymbolAddress((void**)&pbits, g_adjbits);
    cudaGetSymbolAddress((void**)&pzA,  g_zA);
    cudaGetSymbolAddress((void**)&pzC,  g_zC);
    cudaGetSymbolAddress((void**)&pzB,  g_zB);

    cudaFuncSetAttribute(scores_hop1_kernel,
        cudaFuncAttributeMaxDynamicSharedMemorySize, FS_SMEM);
    cudaFuncSetAttribute(hop_kernel8<false>,
        cudaFuncAttributeMaxDynamicSharedMemorySize, HOP_SMEM);
    cudaFuncSetAttribute(hop_kernel8<true>,
        cudaFuncAttributeMaxDynamicSharedMemorySize, HOP_SMEM);

    prologue_kernel<<<PACK_BLKS + (NX4 + 3 * NW4) / 256, 256>>>(
        (const float4*)x, (const float4*)Wq, (const float4*)Wk, (const float4*)Wv,
        adj, (__nv_bfloat162*)pxb, (__nv_bfloat162*)pwb, pbits);

    qkv_kernel<<<dim3(Hc / 128, (Bc * Nc) / 128, 3), 256>>>(
        pxb, pwb, bq, bk, bv, pq, pk, pz0);

    scores_hop1_kernel<<<dim3(Nc / 128, Bc * NHEADS), 256, FS_SMEM>>>(
        pq, pk, pz0, pbits, pP, prs, pzA);

    dim3 gHop(Nc / 128, Bc * NHEADS);
    // serpentine: scores wrote P forward -> hop2 rev -> hop3 fwd -> hop4 rev
    hop_kernel8<false><<<gHop, 256, HOP_SMEM>>>(pP, prs, pzA, pz0, pzC, 1);
    hop_kernel8<false><<<gHop, 256, HOP_SMEM>>>(pP, prs, pzC, pz0, pzA, 0);
    hop_kernel8<true><<<gHop, 256, HOP_SMEM>>>(pP, prs, pzA, pz0, pzB, 1);

    out_kernel<<<Bc * Nc / 8, 256>>>(x, pzB, gamma, beta, out);
}

// round 15
// speedup vs baseline: 1.0860x; 1.0860x over previous
#include <cuda_runtime.h>
#include <cuda_bf16.h>
#include <cstdint>

#define Bc 8
#define Nc 1024
#define Hc 512
#define NHEADS 8
#define HD 64
#define LN_EPS 1e-5f
#define LOG2E 1.44269504088896f

typedef __nv_bfloat16 bf16;

// ---------------- scratch ------------------------------------------------------
__device__ bf16  g_xb[Bc * Nc * Hc];
__device__ bf16  g_wb[3 * Hc * Hc];
__device__ bf16  g_q[Bc * NHEADS * Nc * HD];             // [bh][n][d] (pre-scaled by log2e)
__device__ bf16  g_k[Bc * NHEADS * Nc * HD];
__device__ bf16  g_z0[Bc * NHEADS * HD * Nc];            // v, d-major [bh][d][n]
__device__ bf16  g_P[(size_t)Bc * NHEADS * Nc * Nc];     // exp(scores), 128MB
__device__ float g_rowsum[Bc * NHEADS * Nc];
__device__ unsigned g_adjbits[Bc * Nc * 32];
__device__ bf16  g_zA[Bc * NHEADS * HD * Nc];            // d-major intermediates
__device__ bf16  g_zC[Bc * NHEADS * HD * Nc];
__device__ bf16  g_zB[Bc * NHEADS * Nc * HD];            // final, token-major bf16

// ---------------- helpers ------------------------------------------------------
__device__ __forceinline__ void mma_bf16(float c[4],
    unsigned a0, unsigned a1, unsigned a2, unsigned a3,
    unsigned b0, unsigned b1)
{
    asm("mma.sync.aligned.m16n8k16.row.col.f32.bf16.bf16.f32 "
        "{%0,%1,%2,%3},{%4,%5,%6,%7},{%8,%9},{%0,%1,%2,%3};"
        : "+f"(c[0]), "+f"(c[1]), "+f"(c[2]), "+f"(c[3])
        : "r"(a0), "r"(a1), "r"(a2), "r"(a3), "r"(b0), "r"(b1));
}
__device__ __forceinline__ void ldsm4(unsigned r[4], unsigned addr) {
    asm volatile("ldmatrix.sync.aligned.m8n8.x4.shared.b16 {%0,%1,%2,%3}, [%4];"
        : "=r"(r[0]), "=r"(r[1]), "=r"(r[2]), "=r"(r[3]) : "r"(addr));
}
__device__ __forceinline__ void stsm4(unsigned addr,
    unsigned r0, unsigned r1, unsigned r2, unsigned r3)
{
    asm volatile("stmatrix.sync.aligned.m8n8.x4.shared.b16 [%0], {%1,%2,%3,%4};"
        :: "r"(addr), "r"(r0), "r"(r1), "r"(r2), "r"(r3));
}
__device__ __forceinline__ void cp16(unsigned smem_dst, const void* gsrc) {
    asm volatile("cp.async.cg.shared.global [%0], [%1], 16;"
                 :: "r"(smem_dst), "l"(gsrc));
}
__device__ __forceinline__ void cp_commit() {
    asm volatile("cp.async.commit_group;");
}
template<int N> __device__ __forceinline__ void cp_wait() {
    asm volatile("cp.async.wait_group %0;" :: "n"(N));
}
__device__ __forceinline__ unsigned packbf(float x, float y) {
    __nv_bfloat162 p;
    p.x = __float2bfloat16_rn(x);
    p.y = __float2bfloat16_rn(y);
    return *(unsigned*)&p;
}

// ---------------- kernel A: fused prologue (pack_adj + cvt bf16) ---------------
#define NX4 (Bc * Nc * Hc / 4)
#define NW4 (Hc * Hc / 4)
#define PACK_BLKS ((Bc * Nc * 32 * 32) / 256)
__global__ __launch_bounds__(256) void prologue_kernel(
    const float4* __restrict__ x,
    const float4* __restrict__ wq, const float4* __restrict__ wk,
    const float4* __restrict__ wv, const int* __restrict__ adj,
    __nv_bfloat162* __restrict__ xb, __nv_bfloat162* __restrict__ wb,
    unsigned* __restrict__ bits)
{
    int blk = blockIdx.x;
    if (blk < PACK_BLKS) {
        int gt = blk * 256 + threadIdx.x;
        int gw = gt >> 5;
        int lane = gt & 31;
        int row = gw >> 5;
        int col = (gw & 31) * 32 + lane;
        int v = adj[(size_t)row * Nc + col];
        unsigned m = __ballot_sync(0xffffffffu, v != 0);
        if (lane == 0) bits[gw] = m;
        return;
    }
    int i = (blk - PACK_BLKS) * 256 + threadIdx.x;
    const float4* src;
    __nv_bfloat162* dst;
    int off;
    if (i < NX4)               { src = x;  dst = xb;            off = i; }
    else if (i < NX4 + NW4)    { src = wq; dst = wb;            off = i - NX4; }
    else if (i < NX4 + 2*NW4)  { src = wk; dst = wb + 2*NW4;    off = i - NX4 - NW4; }
    else                       { src = wv; dst = wb + 4*NW4;    off = i - NX4 - 2*NW4; }
    float4 v = src[off];
    __nv_bfloat162 a, b;
    a.x = __float2bfloat16_rn(v.x); a.y = __float2bfloat16_rn(v.y);
    b.x = __float2bfloat16_rn(v.z); b.y = __float2bfloat16_rn(v.w);
    dst[2 * off] = a; dst[2 * off + 1] = b;
}

// ---------------- kernel 1: QKV GEMM, all-bf16 (round-13 version) --------------
__global__ __launch_bounds__(256) void qkv_kernel(
    const bf16* __restrict__ Xb, const bf16* __restrict__ Wb,
    const float* __restrict__ bq, const float* __restrict__ bk,
    const float* __restrict__ bv,
    bf16* __restrict__ outq, bf16* __restrict__ outk, bf16* __restrict__ outv)
{
    const int which = blockIdx.z;
    const bf16* W = Wb + (size_t)which * Hc * Hc;
    const float* bias = which == 0 ? bq : which == 1 ? bk : bv;

    __shared__ uint32_t Xs[128 * 36];
    __shared__ uint32_t Ws[128 * 36];

    const int tid = threadIdx.x;
    const int wid = tid >> 5, lane = tid & 31;
    const int g = lane >> 2, t = lane & 3;
    const int warpM = (wid >> 1) * 32;
    const int warpN = (wid & 1) * 64;
    const int mBase = blockIdx.y * 128;
    const int nBase = blockIdx.x * 128;

    float acc[2][8][4] = {};

    for (int k0 = 0; k0 < Hc; k0 += 64) {
        #pragma unroll
        for (int it = 0; it < 4; it++) {
            int j = tid + it * 256;
            int r = j >> 3, c = j & 7;
            *(uint4*)&Xs[r * 36 + c * 4] =
                *(const uint4*)&Xb[(size_t)(mBase + r) * Hc + k0 + c * 8];
            *(uint4*)&Ws[r * 36 + c * 4] =
                *(const uint4*)&W[(size_t)(nBase + r) * Hc + k0 + c * 8];
        }
        __syncthreads();
        #pragma unroll
        for (int ks = 0; ks < 32; ks += 8) {
            unsigned a[2][4], b[8][2];
            #pragma unroll
            for (int mf = 0; mf < 2; mf++) {
                int r0 = warpM + mf * 16 + g;
                a[mf][0] = Xs[r0 * 36 + ks + t];
                a[mf][1] = Xs[(r0 + 8) * 36 + ks + t];
                a[mf][2] = Xs[r0 * 36 + ks + t + 4];
                a[mf][3] = Xs[(r0 + 8) * 36 + ks + t + 4];
            }
            #pragma unroll
            for (int nf = 0; nf < 8; nf++) {
                int nr = warpN + nf * 8 + g;
                b[nf][0] = Ws[nr * 36 + ks + t];
                b[nf][1] = Ws[nr * 36 + ks + t + 4];
            }
            #pragma unroll
            for (int mf = 0; mf < 2; mf++)
                #pragma unroll
                for (int nf = 0; nf < 8; nf++)
                    mma_bf16(acc[mf][nf], a[mf][0], a[mf][1], a[mf][2], a[mf][3],
                             b[nf][0], b[nf][1]);
        }
        __syncthreads();
    }

    const float qscale = (which == 0) ? LOG2E : 1.0f;
    #pragma unroll
    for (int mf = 0; mf < 2; mf++)
        #pragma unroll
        for (int nf = 0; nf < 8; nf++)
            #pragma unroll
            for (int half = 0; half < 2; half++) {
                int row = mBase + warpM + mf * 16 + g + half * 8;
                int col = nBase + warpN + nf * 8 + 2 * t;
                float v0 = (acc[mf][nf][half * 2 + 0] + bias[col]) * qscale;
                float v1 = (acc[mf][nf][half * 2 + 1] + bias[col + 1]) * qscale;
                int btok = row >> 10, ntok = row & 1023;
                int h = col >> 6, d = col & 63;
                int bh = btok * NHEADS + h;
                if (which == 2) {
                    outv[((size_t)bh * HD + d) * Nc + ntok] = __float2bfloat16_rn(v0);
                    outv[((size_t)bh * HD + d + 1) * Nc + ntok] = __float2bfloat16_rn(v1);
                } else {
                    bf16* out = which == 0 ? outq : outk;
                    __nv_bfloat162 pr;
                    pr.x = __float2bfloat16_rn(v0);
                    pr.y = __float2bfloat16_rn(v1);
                    *(__nv_bfloat162*)&out[((size_t)bh * Nc + ntok) * HD + d] = pr;
                }
            }
}

// ---------------- kernel 2: scores + hop1 fused (round-13 ordering) ------------
#define FQ_W (128 * 36)
#define FK2_W (128 * 32)
#define FZ2_W (64 * 64)
#define PSTG_W (128 * 32)
#define FS_SMEM ((FQ_W + 2 * FK2_W + 2 * FZ2_W + PSTG_W) * 4)   // 100352 B

__global__ __launch_bounds__(256, 2) void scores_hop1_kernel(
    const bf16* __restrict__ q, const bf16* __restrict__ k,
    const bf16* __restrict__ z0_tr, const unsigned* __restrict__ adjbits,
    bf16* __restrict__ P, float* __restrict__ rowsum, bf16* __restrict__ z1)
{
    extern __shared__ __align__(16) char smem[];
    uint32_t* Qs = (uint32_t*)smem;
    unsigned sbase = (unsigned)__cvta_generic_to_shared(smem);
    const unsigned kbase = sbase + FQ_W * 4;
    const unsigned zbase = kbase + 2 * FK2_W * 4;
    const unsigned pstg = zbase + 2 * FZ2_W * 4;
    const uint32_t* stw = (const uint32_t*)(smem + (FQ_W + 2 * FK2_W + 2 * FZ2_W) * 4);

    const int bh = blockIdx.y;
    const int b = bh >> 3;
    const int nBase = blockIdx.x * 128;

    const int tid = threadIdx.x;
    const int wid = tid >> 5, lane = tid & 31;
    const int g = lane >> 2, t = lane & 3;
    const int warpRow = wid * 16;

    const bf16* qb = q + (size_t)bh * Nc * HD;
    const bf16* kb = k + (size_t)bh * Nc * HD;
    const bf16* zi = z0_tr + (size_t)bh * HD * Nc;

    const int q4 = lane >> 3;
    const int selB = q4 & 1;
    const int rBoff = ((q4 >> 1) << 3) + (lane & 7);
    const int xorB = lane & 7;
    const int lr8 = lane & 7;
    const int lm = lane >> 3;

    #pragma unroll
    for (int it = 0; it < 4; it++) {
        int j = tid + it * 256;
        int r = j >> 3, c = j & 7;
        *(uint4*)&Qs[r * 36 + c * 4] =
            *(const uint4*)&qb[(size_t)(nBase + r) * HD + c * 8];
    }

    auto loadKZ = [&](int ct, int s) {
        unsigned kb2 = kbase + s * (FK2_W * 4);
        #pragma unroll
        for (int j = 0; j < 4; j++) {
            int e = tid + j * 256;
            int r = e >> 3, c = e & 7;
            cp16(kb2 + (r * 8 + (c ^ (r & 7))) * 16,
                 kb + (size_t)(ct * 128 + r) * HD + c * 8);
        }
        unsigned zb2 = zbase + s * (FZ2_W * 4);
        #pragma unroll
        for (int j = 0; j < 4; j++) {
            int e = tid + j * 256;
            int d = e >> 4, c = e & 15;
            cp16(zb2 + (d * 16 + ((c & 8) | ((c & 7) ^ (d & 7)))) * 16,
                 zi + (size_t)d * Nc + ct * 128 + c * 8);
        }
        cp_commit();
    };
    loadKZ(0, 0);
    loadKZ(1, 1);
    __syncthreads();

    unsigned qf[4][4];
    #pragma unroll
    for (int ks = 0; ks < 4; ks++) {
        int r0 = warpRow + g;
        qf[ks][0] = Qs[r0 * 36 + ks * 8 + t];
        qf[ks][1] = Qs[(r0 + 8) * 36 + ks * 8 + t];
        qf[ks][2] = Qs[r0 * 36 + ks * 8 + t + 4];
        qf[ks][3] = Qs[(r0 + 8) * 36 + ks * 8 + t + 4];
    }

    const unsigned* bitsb = adjbits + (size_t)b * Nc * 32;
    bf16* Pb = P + (size_t)bh * Nc * Nc;
    const int row_g = nBase + warpRow + g;
    const int row_h = row_g + 8;
    const int tshift = 2 * t;

    float accz[8][4] = {};
    float rs_g = 0.f, rs_h = 0.f;

    for (int ct = 0; ct < 8; ct++) {
        if (ct < 7) cp_wait<1>(); else cp_wait<0>();
        __syncthreads();
        const int buf = ct & 1;
        const unsigned kbyte = kbase + buf * (FK2_W * 4);
        const unsigned zbyte = zbase + buf * (FZ2_W * 4);

        #pragma unroll
        for (int half = 0; half < 2; half++) {
            // ---- scores MMA ----
            float accs[8][4] = {};
            #pragma unroll
            for (int ksi = 0; ksi < 4; ksi++) {
                const unsigned chsw = (unsigned)((ksi * 2 + selB) ^ xorB) << 4;
                #pragma unroll
                for (int grp = 0; grp < 4; grp++) {
                    unsigned kf[4];
                    ldsm4(kf, kbyte + (unsigned)(half * 64 + grp * 16 + rBoff) * 128 + chsw);
                    mma_bf16(accs[2 * grp],     qf[ksi][0], qf[ksi][1], qf[ksi][2], qf[ksi][3], kf[0], kf[1]);
                    mma_bf16(accs[2 * grp + 1], qf[ksi][0], qf[ksi][1], qf[ksi][2], qf[ksi][3], kf[2], kf[3]);
                }
            }

            // ---- mask (pre-shifted, constant-shift extract) + exp2 + pack ----
            unsigned prg[8], prh[8];
            unsigned m0g = bitsb[(size_t)row_g * 32 + ct * 4 + half * 2] >> tshift;
            unsigned m1g = bitsb[(size_t)row_g * 32 + ct * 4 + half * 2 + 1] >> tshift;
            unsigned m0h = bitsb[(size_t)row_h * 32 + ct * 4 + half * 2] >> tshift;
            unsigned m1h = bitsb[(size_t)row_h * 32 + ct * 4 + half * 2 + 1] >> tshift;
            #pragma unroll
            for (int nf = 0; nf < 8; nf++) {
                unsigned mg_ = ((nf < 4) ? m0g : m1g) >> ((nf & 3) * 8);
                unsigned mh_ = ((nf < 4) ? m0h : m1h) >> ((nf & 3) * 8);
                float e0 = (mg_ & 1u) ? exp2f(accs[nf][0]) : 0.f;
                float e1 = (mg_ & 2u) ? exp2f(accs[nf][1]) : 0.f;
                float e2 = (mh_ & 1u) ? exp2f(accs[nf][2]) : 0.f;
                float e3 = (mh_ & 2u) ? exp2f(accs[nf][3]) : 0.f;
                prg[nf] = packbf(e0, e1);
                prh[nf] = packbf(e2, e3);
                rs_g += e0 + e1;
                rs_h += e2 + e3;
            }

            // ---- z-MMA: A = exp fragments, B = z0 via ldmatrix ----
            #pragma unroll
            for (int kc = 0; kc < 4; kc++) {
                unsigned a0 = prg[2 * kc], a1 = prh[2 * kc];
                unsigned a2 = prg[2 * kc + 1], a3 = prh[2 * kc + 1];
                const unsigned chsw = (unsigned)((half * 8 + kc * 2 + selB) ^ xorB) << 4;
                #pragma unroll
                for (int grp = 0; grp < 4; grp++) {
                    unsigned zf[4];
                    ldsm4(zf, zbyte + (unsigned)(grp * 16 + rBoff) * 256 + chsw);
                    mma_bf16(accz[2 * grp],     a0, a1, a2, a3, zf[0], zf[1]);
                    mma_bf16(accz[2 * grp + 1], a0, a1, a2, a3, zf[2], zf[3]);
                }
            }

            // ---- P store: stmatrix stage -> coalesced STG.128 ----
            {
                int r1 = warpRow + lr8;
                int r2 = r1 + 8;
                stsm4(pstg + (unsigned)(r1 * 8 + (lm ^ (r1 & 7))) * 16,
                      prg[0], prg[1], prg[2], prg[3]);
                stsm4(pstg + (unsigned)(r1 * 8 + ((4 + lm) ^ (r1 & 7))) * 16,
                      prg[4], prg[5], prg[6], prg[7]);
                stsm4(pstg + (unsigned)(r2 * 8 + (lm ^ (r2 & 7))) * 16,
                      prh[0], prh[1], prh[2], prh[3]);
                stsm4(pstg + (unsigned)(r2 * 8 + ((4 + lm) ^ (r2 & 7))) * 16,
                      prh[4], prh[5], prh[6], prh[7]);
                __syncwarp();
                #pragma unroll
                for (int i = 0; i < 4; i++) {
                    int idx = i * 32 + lane;
                    int lr = warpRow + (idx >> 3);
                    int ch = idx & 7;
                    uint4 v = *(const uint4*)&stw[(lr * 8 + (ch ^ (lr & 7))) * 4];
                    *(uint4*)&Pb[(size_t)(nBase + lr) * Nc + ct * 128 + half * 64 + ch * 8] = v;
                }
                __syncwarp();
            }
        }
        __syncthreads();
        if (ct + 2 < 8) loadKZ(ct + 2, buf);
    }

    rs_g += __shfl_xor_sync(0xffffffffu, rs_g, 1);
    rs_g += __shfl_xor_sync(0xffffffffu, rs_g, 2);
    rs_h += __shfl_xor_sync(0xffffffffu, rs_h, 1);
    rs_h += __shfl_xor_sync(0xffffffffu, rs_h, 2);
    if (t == 0) {
        rowsum[(size_t)bh * Nc + row_g] = rs_g;
        rowsum[(size_t)bh * Nc + row_h] = rs_h;
    }

    float sc_g = 0.9f / rs_g, sc_h = 0.9f / rs_h;
    bf16* zo = z1 + (size_t)bh * HD * Nc;
    #pragma unroll
    for (int nd = 0; nd < 8; nd++) {
        int d0 = nd * 8 + 2 * t;
        float zg0 = __bfloat162float(zi[(size_t)d0 * Nc + row_g]);
        float zg1 = __bfloat162float(zi[(size_t)(d0 + 1) * Nc + row_g]);
        float zh0 = __bfloat162float(zi[(size_t)d0 * Nc + row_h]);
        float zh1 = __bfloat162float(zi[(size_t)(d0 + 1) * Nc + row_h]);
        zo[(size_t)d0 * Nc + row_g]       = __float2bfloat16_rn(accz[nd][0] * sc_g + 0.1f * zg0);
        zo[(size_t)(d0 + 1) * Nc + row_g] = __float2bfloat16_rn(accz[nd][1] * sc_g + 0.1f * zg1);
        zo[(size_t)d0 * Nc + row_h]       = __float2bfloat16_rn(accz[nd][2] * sc_h + 0.1f * zh0);
        zo[(size_t)(d0 + 1) * Nc + row_h] = __float2bfloat16_rn(accz[nd][3] * sc_h + 0.1f * zh1);
    }
}

// ---------------- kernel 3: hop, K=64 2-stage swizzled, ldmatrix, 4 CTA/SM -----
#define PSW_W (128 * 32)
#define ZSW_W (64 * 32)
#define STG_W (PSW_W + ZSW_W)            // 24576 B
#define HOP_SMEM (2 * STG_W * 4)         // 49152 B

template<bool LAST>
__global__ __launch_bounds__(256, 4) void hop_kernel8(
    const bf16* __restrict__ Pg, const float* __restrict__ rowsum,
    const bf16* __restrict__ zin_tr, const bf16* __restrict__ z0_tr,
    void* __restrict__ zout, int rev)
{
    extern __shared__ __align__(16) char smem[];
    unsigned sbase = (unsigned)__cvta_generic_to_shared(smem);

    int lin = blockIdx.y * gridDim.x + blockIdx.x;
    if (rev) lin = 511 - lin;
    const int bh = lin >> 3;
    const int mBase = (lin & 7) * 128;

    const bf16* Pb = Pg + (size_t)bh * Nc * Nc;
    const bf16* zi = zin_tr + (size_t)bh * HD * Nc;

    const int tid = threadIdx.x;
    const int wid = tid >> 5, lane = tid & 31;
    const int g = lane >> 2, t = lane & 3;
    const int warpM = (wid >> 1) * 32;
    const int warpN = (wid & 1) * 32;

    const int l15 = lane & 15;
    const int selA = lane >> 4;
    const int xorA = l15 & 7;
    const int q4 = lane >> 3;
    const int selB = q4 & 1;
    const int rBoff = ((q4 >> 1) << 3) + (lane & 7);
    const int xorB = lane & 7;
    const unsigned baseA0 = (unsigned)(warpM + l15) * 128;
    const unsigned baseA1 = baseA0 + 2048;
    const unsigned baseB0 = (unsigned)(warpN + rBoff) * 128;
    const unsigned baseB1 = baseB0 + 2048;

    auto load_chunk = [&](int ck, int s) {
        unsigned pbase = sbase + s * (STG_W * 4);
        unsigned zbase = pbase + PSW_W * 4;
        const int k0 = ck * 64;
        #pragma unroll
        for (int j = 0; j < 4; j++) {
            int e = tid + j * 256;
            int r = e >> 3, ch = e & 7;
            cp16(pbase + (r * 8 + (ch ^ (r & 7))) * 16,
                 Pb + (size_t)(mBase + r) * Nc + k0 + ch * 8);
        }
        #pragma unroll
        for (int j = 0; j < 2; j++) {
            int e = tid + j * 256;
            int d = e >> 3, ch = e & 7;
            cp16(zbase + (d * 8 + (ch ^ (d & 7))) * 16,
                 zi + (size_t)d * Nc + k0 + ch * 8);
        }
        cp_commit();
    };

    load_chunk(0, 0);
    load_chunk(1, 1);

    float acc[2][4][4] = {};

    for (int c = 0; c < 16; c++) {
        if (c < 15) cp_wait<1>(); else cp_wait<0>();
        __syncthreads();
        const int st = c & 1;
        const unsigned pbyte = sbase + st * (STG_W * 4);
        const unsigned zbyte = pbyte + PSW_W * 4;
        #pragma unroll
        for (int ks = 0; ks < 32; ks += 8) {
            const int cc = ks >> 2;
            unsigned aA0[4], aA1[4], bB0[4], bB1[4];
            ldsm4(aA0, pbyte + baseA0 + ((unsigned)((cc + selA) ^ xorA) << 4));
            ldsm4(aA1, pbyte + baseA1 + ((unsigned)((cc + selA) ^ xorA) << 4));
            ldsm4(bB0, zbyte + baseB0 + ((unsigned)((cc + selB) ^ xorB) << 4));
            ldsm4(bB1, zbyte + baseB1 + ((unsigned)((cc + selB) ^ xorB) << 4));
            mma_bf16(acc[0][0], aA0[0], aA0[1], aA0[2], aA0[3], bB0[0], bB0[1]);
            mma_bf16(acc[0][1], aA0[0], aA0[1], aA0[2], aA0[3], bB0[2], bB0[3]);
            mma_bf16(acc[0][2], aA0[0], aA0[1], aA0[2], aA0[3], bB1[0], bB1[1]);
            mma_bf16(acc[0][3], aA0[0], aA0[1], aA0[2], aA0[3], bB1[2], bB1[3]);
            mma_bf16(acc[1][0], aA1[0], aA1[1], aA1[2], aA1[3], bB0[0], bB0[1]);
            mma_bf16(acc[1][1], aA1[0], aA1[1], aA1[2], aA1[3], bB0[2], bB0[3]);
            mma_bf16(acc[1][2], aA1[0], aA1[1], aA1[2], aA1[3], bB1[0], bB1[1]);
            mma_bf16(acc[1][3], aA1[0], aA1[1], aA1[2], aA1[3], bB1[2], bB1[3]);
        }
        __syncthreads();
        if (c + 2 < 16) load_chunk(c + 2, st);
    }

    #pragma unroll
    for (int mf = 0; mf < 2; mf++)
        #pragma unroll
        for (int half = 0; half < 2; half++) {
            int row = mBase + warpM + mf * 16 + g + half * 8;
            float scale = 0.9f / rowsum[(size_t)bh * Nc + row];
            #pragma unroll
            for (int nf = 0; nf < 4; nf++) {
                int col = warpN + nf * 8 + 2 * t;
                float z00 = __bfloat162float(z0_tr[((size_t)bh * HD + col) * Nc + row]);
                float z01 = __bfloat162float(z0_tr[((size_t)bh * HD + col + 1) * Nc + row]);
                float v0 = acc[mf][nf][half * 2 + 0] * scale + 0.1f * z00;
                float v1 = acc[mf][nf][half * 2 + 1] * scale + 0.1f * z01;
                if (LAST) {
                    bf16* zf = (bf16*)zout;
                    *(unsigned*)&zf[((size_t)bh * Nc + row) * HD + col] = packbf(v0, v1);
                } else {
                    bf16* zo = (bf16*)zout;
                    zo[((size_t)bh * HD + col) * Nc + row] = __float2bfloat16_rn(v0);
                    zo[((size_t)bh * HD + col + 1) * Nc + row] = __float2bfloat16_rn(v1);
                }
            }
        }
}

// ---------------- kernel 4: residual + layernorm (warp-per-row) ---------------
__global__ __launch_bounds__(256) void out_kernel(
    const float* __restrict__ x, const bf16* __restrict__ z,
    const float* __restrict__ gamma, const float* __restrict__ beta,
    float* __restrict__ out)
{
    const int wid = threadIdx.x >> 5, lane = threadIdx.x & 31;
    const int row = blockIdx.x * 8 + wid;
    const int b = row >> 10, n = row & (Nc - 1);

    const float4* xr = (const float4*)(x + (size_t)row * Hc);
    float y[16];
    float s = 0.f, s2 = 0.f;
    #pragma unroll
    for (int j = 0; j < 4; j++) {
        int f4 = j * 32 + lane;
        float4 xv = xr[f4];
        int e = f4 * 4;
        int h = e >> 6, d = e & 63;
        const bf16* zp = z + (((size_t)b * NHEADS + h) * Nc + n) * HD + d;
        uint2 zv = *(const uint2*)zp;
        __nv_bfloat162 z01 = *(__nv_bfloat162*)&zv.x;
        __nv_bfloat162 z23 = *(__nv_bfloat162*)&zv.y;
        float y0 = xv.x + __bfloat162float(z01.x);
        float y1 = xv.y + __bfloat162float(z01.y);
        float y2 = xv.z + __bfloat162float(z23.x);
        float y3 = xv.w + __bfloat162float(z23.y);
        y[j*4+0] = y0; y[j*4+1] = y1; y[j*4+2] = y2; y[j*4+3] = y3;
        s += y0 + y1 + y2 + y3;
        s2 += y0*y0 + y1*y1 + y2*y2 + y3*y3;
    }
    #pragma unroll
    for (int o = 16; o > 0; o >>= 1) {
        s  += __shfl_xor_sync(0xffffffffu, s, o);
        s2 += __shfl_xor_sync(0xffffffffu, s2, o);
    }
    float mu = s * (1.0f / Hc);
    float var = s2 * (1.0f / Hc) - mu * mu;
    float rstd = rsqrtf(var + LN_EPS);

    const float4* gm = (const float4*)gamma;
    const float4* bt = (const float4*)beta;
    float4* outr = (float4*)(out + (size_t)row * Hc);
    #pragma unroll
    for (int j = 0; j < 4; j++) {
        int f4 = j * 32 + lane;
        float4 gv = gm[f4], bv = bt[f4];
        float4 ov;
        ov.x = (y[j*4+0] - mu) * rstd * gv.x + bv.x;
        ov.y = (y[j*4+1] - mu) * rstd * gv.y + bv.y;
        ov.z = (y[j*4+2] - mu) * rstd * gv.z + bv.z;
        ov.w = (y[j*4+3] - mu) * rstd * gv.w + bv.w;
        outr[f4] = ov;
    }
}

// ---------------- launch -------------------------------------------------------
extern "C" void kernel_launch(void* const* d_in, const int* in_sizes, int n_in,
                              void* d_out, int out_size)
{
    const float* x     = (const float*)d_in[0];
    const int*   adj   = (const int*)d_in[1];
    const float* Wq    = (const float*)d_in[2];
    const float* bq    = (const float*)d_in[3];
    const float* Wk    = (const float*)d_in[4];
    const float* bk    = (const float*)d_in[5];
    const float* Wv    = (const float*)d_in[6];
    const float* bv    = (const float*)d_in[7];
    const float* gamma = (const float*)d_in[8];
    const float* beta  = (const float*)d_in[9];
    float* out = (float*)d_out;

    float* prs;
    bf16 *pxb, *pwb, *pq, *pk, *pz0, *pP, *pzA, *pzC, *pzB;
    unsigned* pbits;
    cudaGetSymbolAddress((void**)&pxb,  g_xb);
    cudaGetSymbolAddress((void**)&pwb,  g_wb);
    cudaGetSymbolAddress((void**)&pq,   g_q);
    cudaGetSymbolAddress((void**)&pk,   g_k);
    cudaGetSymbolAddress((void**)&pz0,  g_z0);
    cudaGetSymbolAddress((void**)&pP,   g_P);
    cudaGetSymbolAddress((void**)&prs,  g_rowsum);
    cudaGetSymbolAddress((void**)&pbits, g_adjbits);
    cudaGetSymbolAddress((void**)&pzA,  g_zA);
    cudaGetSymbolAddress((void**)&pzC,  g_zC);
    cudaGetSymbolAddress((void**)&pzB,  g_zB);

    cudaFuncSetAttribute(scores_hop1_kernel,
        cudaFuncAttributeMaxDynamicSharedMemorySize, FS_SMEM);
    cudaFuncSetAttribute(hop_kernel8<false>,
        cudaFuncAttributeMaxDynamicSharedMemorySize, HOP_SMEM);
    cudaFuncSetAttribute(hop_kernel8<true>,
        cudaFuncAttributeMaxDynamicSharedMemorySize, HOP_SMEM);

    prologue_kernel<<<PACK_BLKS + (NX4 + 3 * NW4) / 256, 256>>>(
        (const float4*)x, (const float4*)Wq, (const float4*)Wk, (const float4*)Wv,
        adj, (__nv_bfloat162*)pxb, (__nv_bfloat162*)pwb, pbits);

    qkv_kernel<<<dim3(Hc / 128, (Bc * Nc) / 128, 3), 256>>>(
        pxb, pwb, bq, bk, bv, pq, pk, pz0);

    scores_hop1_kernel<<<dim3(Nc / 128, Bc * NHEADS), 256, FS_SMEM>>>(
        pq, pk, pz0, pbits, pP, prs, pzA);

    dim3 gHop(Nc / 128, Bc * NHEADS);
    // serpentine: scores wrote P forward -> hop2 rev -> hop3 fwd -> hop4 rev
    hop_kernel8<false><<<gHop, 256, HOP_SMEM>>>(pP, prs, pzA, pz0, pzC, 1);
    hop_kernel8<false><<<gHop, 256, HOP_SMEM>>>(pP, prs, pzC, pz0, pzA, 0);
    hop_kernel8<true><<<gHop, 256, HOP_SMEM>>>(pP, prs, pzA, pz0, pzB, 1);

    out_kernel<<<Bc * Nc / 8, 256>>>(x, pzB, gamma, beta, out);
}